// round 17
// baseline (speedup 1.0000x reference)
#include <cuda_runtime.h>
#include <cuda_bf16.h>
#include <stdint.h>

#define NN 50000
#define NE 600000
#define SCAN_BLOCKS ((NN + 1 + 1023) / 1024)   // 49

// ---- static device scratch ----
__device__ int   g_deg[NN + 1];
__device__ int   g_off[NN + 1];
__device__ int   g_cur[NN];
__device__ int   g_srcs[NE];
__device__ unsigned long long g_descs[64];
__device__ __align__(16) float         g_bufF[NN * 128];            // fp32 h (agg input)
__device__ __align__(16) __nv_bfloat16 g_bufHi[NN * 128];           // split A for GEMMs
__device__ __align__(16) __nv_bfloat16 g_bufLo[NN * 128];
__device__ __align__(16) __nv_bfloat16 g_bufHi2[NN * 128];          // gemm2 -> gemm3
__device__ __align__(16) __nv_bfloat16 g_bufLo2[NN * 128];
// prepped weights: tiles 0..4 = W0,W1,W2,Wm1[:,0:128],Wm1[:,128:256] as Wt[n][k] 128x128
// (hi/lo bf16 split); appended at offset 81920: Wm2t padded [16][k<=263] stride 264
#define WM2_GOFF 81920
__device__ __align__(256) __nv_bfloat16 g_Bhi[5 * 16384 + 16 * 264];
__device__ __align__(256) __nv_bfloat16 g_Blo[5 * 16384 + 16 * 264];

// ===================== warp MMA helpers (base-target safe: sm_80+) =====================
__device__ __forceinline__ uint32_t smem_u32(const void* p) {
    uint32_t a;
    asm("{ .reg .u64 t; cvta.to.shared.u64 t, %1; cvt.u32.u64 %0, t; }" : "=r"(a) : "l"(p));
    return a;
}
__device__ __forceinline__ void ldsm_x4(uint32_t* a, uint32_t addr) {
    asm volatile("ldmatrix.sync.aligned.m8n8.x4.shared.b16 {%0,%1,%2,%3}, [%4];"
                 : "=r"(a[0]), "=r"(a[1]), "=r"(a[2]), "=r"(a[3]) : "r"(addr));
}
__device__ __forceinline__ void ldsm_x2(uint32_t* b, uint32_t addr) {
    asm volatile("ldmatrix.sync.aligned.m8n8.x2.shared.b16 {%0,%1}, [%2];"
                 : "=r"(b[0]), "=r"(b[1]) : "r"(addr));
}
__device__ __forceinline__ void mma_bf16(float* c, const uint32_t* a, const uint32_t* b) {
    asm volatile("mma.sync.aligned.m16n8k16.row.col.f32.bf16.bf16.f32 "
                 "{%0,%1,%2,%3}, {%4,%5,%6,%7}, {%8,%9}, {%0,%1,%2,%3};"
                 : "+f"(c[0]), "+f"(c[1]), "+f"(c[2]), "+f"(c[3])
                 : "r"(a[0]), "r"(a[1]), "r"(a[2]), "r"(a[3]), "r"(b[0]), "r"(b[1]));
}

// ===================== weight prep (+ deg/descs zero) =====================
#define PREP_TOTAL (5 * 16384 + 16 * 264)
__global__ void prep_w_kernel(const float* __restrict__ W0, const float* __restrict__ W1,
                              const float* __restrict__ W2, const float* __restrict__ Wm1,
                              const float* __restrict__ Wm2,
                              __nv_bfloat16* __restrict__ bhi, __nv_bfloat16* __restrict__ blo,
                              int* __restrict__ deg, unsigned long long* __restrict__ descs) {
    int idx = blockIdx.x * blockDim.x + threadIdx.x;
    if (idx <= NN) deg[idx] = 0;
    if (idx < 64) descs[idx] = 0ull;
    if (idx >= PREP_TOTAL) return;
    float w;
    if (idx < 5 * 16384) {
        int t = idx >> 14;
        int e = idx & 16383;
        int n = e >> 7, k = e & 127;
        if (t == 0)      w = W0[k * 128 + n];
        else if (t == 1) w = W1[k * 128 + n];
        else if (t == 2) w = W2[k * 128 + n];
        else             w = Wm1[k * 256 + (t - 3) * 128 + n];
    } else {
        int e = idx - 5 * 16384;
        int n = e / 264, k = e % 264;
        w = (n < 10 && k < 256) ? Wm2[k * 10 + n] : 0.f;
    }
    __nv_bfloat16 h = __float2bfloat16(w);
    __nv_bfloat16 l = __float2bfloat16(w - __bfloat162float(h));
    bhi[idx] = h;
    blo[idx] = l;
}

// ===================== CSR build =====================
__global__ void hist_kernel(const int* __restrict__ dst, int* __restrict__ deg) {
    int e = blockIdx.x * blockDim.x + threadIdx.x;
    if (e < NE) atomicAdd(&deg[dst[e]], 1);
}
// single-pass exclusive scan, warp-parallel decoupled lookback (packed 64-bit descs)
__global__ void scanfused_kernel(const int* __restrict__ deg, int* __restrict__ off,
                                 int* __restrict__ cur,
                                 volatile unsigned long long* descs) {
    __shared__ int wsum[32];
    __shared__ int sPrefix;
    const int b = blockIdx.x;
    int i = b * 1024 + threadIdx.x;
    int v = (i < NN) ? deg[i] : 0;
    int lane = threadIdx.x & 31, w = threadIdx.x >> 5;
    int inc = v;
    #pragma unroll
    for (int o = 1; o < 32; o <<= 1) {
        int t = __shfl_up_sync(0xffffffffu, inc, o);
        if (lane >= o) inc += t;
    }
    if (lane == 31) wsum[w] = inc;
    __syncthreads();
    if (w == 0) {
        int s = wsum[lane];
        #pragma unroll
        for (int o = 1; o < 32; o <<= 1) {
            int t = __shfl_up_sync(0xffffffffu, s, o);
            if (lane >= o) s += t;
        }
        wsum[lane] = s;
    }
    __syncthreads();
    int prefix = (w > 0) ? wsum[w - 1] : 0;
    int blockTotal = wsum[31];
    if (threadIdx.x == 0)
        descs[b] = (1ull << 32) | (unsigned)blockTotal;   // aggregate available
    if (w == 0) {
        int p = 0;
        if (b > 0) {
            int base = b - 1;
            bool done = false;
            while (!done) {
                int j = base - lane;                       // lane0 = nearest predecessor
                unsigned long long d = (j >= 0) ? descs[j] : (2ull << 32);
                unsigned st = (unsigned)(d >> 32);
                if (__all_sync(0xffffffffu, st != 0u)) {
                    unsigned pmask = __ballot_sync(0xffffffffu, st == 2u);
                    int firstP = pmask ? (__ffs(pmask) - 1) : 32;
                    int val = (int)(unsigned)(d & 0xffffffffu);
                    int contrib = (lane <= firstP) ? val : 0;
                    #pragma unroll
                    for (int o = 16; o; o >>= 1)
                        contrib += __shfl_down_sync(0xffffffffu, contrib, o);
                    contrib = __shfl_sync(0xffffffffu, contrib, 0);
                    p += contrib;
                    if (firstP < 32) done = true;
                    else             base -= 32;
                }
            }
        }
        if (lane == 0) {
            descs[b] = (2ull << 32) | (unsigned)(p + blockTotal);
            sPrefix = p;
        }
    }
    __syncthreads();
    if (i <= NN) {
        int o = sPrefix + prefix + inc - v;
        off[i] = o;
        if (i < NN) cur[i] = o;
    }
}
__global__ void scatter_kernel(const int* __restrict__ src, const int* __restrict__ dst,
                               int* __restrict__ cur, int* __restrict__ srcs) {
    int e = blockIdx.x * blockDim.x + threadIdx.x;
    if (e < NE) {
        int p = atomicAdd(&cur[dst[e]], 1);
        srcs[p] = src[e];
    }
}

// ===================== GIN aggregate (fp32 gather -> bf16 hi/lo split output) =====================
__global__ void agg_kernel(const float4* __restrict__ x, const int* __restrict__ off,
                           const int* __restrict__ srcs,
                           uint2* __restrict__ outHi, uint2* __restrict__ outLo) {
    int gw   = (blockIdx.x * blockDim.x + threadIdx.x) >> 5;
    int lane = threadIdx.x & 31;
    if (gw >= NN) return;
    int s = off[gw], e = off[gw + 1];
    float4 acc = x[gw * 32 + lane];
    #pragma unroll 2
    for (int i = s; i < e; i++) {
        int sc   = __ldg(&srcs[i]);
        float4 v = x[sc * 32 + lane];
        acc.x += v.x; acc.y += v.y; acc.z += v.z; acc.w += v.w;
    }
    __nv_bfloat162 h0 = __floats2bfloat162_rn(acc.x, acc.y);
    __nv_bfloat162 h1 = __floats2bfloat162_rn(acc.z, acc.w);
    float2 f0 = __bfloat1622float2(h0);
    float2 f1 = __bfloat1622float2(h1);
    __nv_bfloat162 l0 = __floats2bfloat162_rn(acc.x - f0.x, acc.y - f0.y);
    __nv_bfloat162 l1 = __floats2bfloat162_rn(acc.z - f1.x, acc.w - f1.y);
    outHi[gw * 32 + lane] = make_uint2(reinterpret_cast<uint32_t&>(h0),
                                       reinterpret_cast<uint32_t&>(h1));
    outLo[gw * 32 + lane] = make_uint2(reinterpret_cast<uint32_t&>(l0),
                                       reinterpret_cast<uint32_t&>(l1));
}

// ===================== tensor-core GEMM (mma.sync bf16 hi/lo split) =====================
// A is ALWAYS pre-split (Ahi/Alo bf16). Output modes:
//   outMode 0: fp32 out (relu+bias) -> feeds next agg
//   outMode 1: bf16 hi/lo split out (relu+bias) -> feeds gemm3
//   doHead:    Wm1 (2 tiles) kept in smem, then head K=256 -> logits
#define LDA      136               // padded bf16 stride (272 B)
#define A_HI     0
#define A_LO     34816
#define B_HI     69632             // bt0 hi (bt1 hi at +34816)
#define B_LO     139264            // bt0 lo (bt1 lo at +34816)
#define SM_BS    208896            // 256 bias floats
#define WM2_HI   209920            // 16 x 264 bf16 = 8448 B
#define WM2_LO   218368
#define SM_BYTES 226816

__global__ void __launch_bounds__(256, 1)
gemm_tc_kernel(const uint2* __restrict__ Ahi, const uint2* __restrict__ Alo,
               const __nv_bfloat16* __restrict__ gBhi,
               const __nv_bfloat16* __restrict__ gBlo,
               const float* __restrict__ bias,
               float* __restrict__ out,
               uint32_t* __restrict__ oHi, uint32_t* __restrict__ oLo,
               int tile0, int outCols, int nBTiles, int outMode,
               int doHead, float* __restrict__ logits, const float* __restrict__ bm2) {
    extern __shared__ char smem[];
    const int tid  = threadIdx.x;
    const int wid  = tid >> 5;
    const int lane = tid & 31;
    const int rowBase = blockIdx.x * 128;

    // ---- load A tile (pre-split bf16 hi/lo, plain copies) ----
    {
        #pragma unroll
        for (int i = 0; i < 16; i++) {
            int lin = tid + i * 256;          // 4096 uint2 per array
            int r   = lin >> 5;
            int c4  = lin & 31;
            int gr  = rowBase + r;
            uint2 hv = make_uint2(0u, 0u), lv = make_uint2(0u, 0u);
            if (gr < NN) { hv = Ahi[gr * 32 + c4]; lv = Alo[gr * 32 + c4]; }
            int boff = r * (LDA * 2) + c4 * 8;
            *reinterpret_cast<uint2*>(smem + A_HI + boff) = hv;
            *reinterpret_cast<uint2*>(smem + A_LO + boff) = lv;
        }
    }
    // ---- load B tiles ----
    for (int bt = 0; bt < nBTiles; bt++) {
        const uint4* shi = reinterpret_cast<const uint4*>(gBhi + (tile0 + bt) * 16384);
        const uint4* slo = reinterpret_cast<const uint4*>(gBlo + (tile0 + bt) * 16384);
        const int dstOff = bt * 34816;
        #pragma unroll
        for (int i = 0; i < 8; i++) {
            int lin = tid + i * 256;          // 2048 uint4
            int n = lin >> 4, q = lin & 15;
            int boff = n * (LDA * 2) + q * 16;
            *reinterpret_cast<uint4*>(smem + B_HI + dstOff + boff) = shi[lin];
            *reinterpret_cast<uint4*>(smem + B_LO + dstOff + boff) = slo[lin];
        }
    }
    for (int i = tid; i < 128 * nBTiles; i += 256)
        reinterpret_cast<float*>(smem + SM_BS)[i] = bias[i];
    if (doHead) {
        const uint4* shiW = reinterpret_cast<const uint4*>(gBhi + WM2_GOFF);
        const uint4* sloW = reinterpret_cast<const uint4*>(gBlo + WM2_GOFF);
        for (int i = tid; i < 528; i += 256) {          // 16*264 bf16 = 528 uint4
            reinterpret_cast<uint4*>(smem + WM2_HI)[i] = shiW[i];
            reinterpret_cast<uint4*>(smem + WM2_LO)[i] = sloW[i];
        }
    }
    __syncthreads();

    const int wm = (wid & 1) * 64;
    const int wn = (wid >> 1) * 32;
    const uint32_t sb = smem_u32(smem);
    const uint32_t aBaseHi = sb + A_HI + (wm + (lane & 15)) * (LDA * 2) + (lane >> 4) * 16;
    const uint32_t aBaseLo = aBaseHi + (A_LO - A_HI);
    const float* bs = reinterpret_cast<const float*>(smem + SM_BS);

    for (int bt = 0; bt < nBTiles; bt++) {
        float acc[4][4][4];
        #pragma unroll
        for (int mt = 0; mt < 4; mt++)
            #pragma unroll
            for (int nt = 0; nt < 4; nt++)
                #pragma unroll
                for (int j = 0; j < 4; j++) acc[mt][nt][j] = 0.f;

        const uint32_t bBaseHi = sb + B_HI + bt * 34816
                               + (wn + (lane & 7)) * (LDA * 2) + ((lane >> 3) & 1) * 16;
        const uint32_t bBaseLo = bBaseHi + (B_LO - B_HI);

        #pragma unroll
        for (int ks = 0; ks < 8; ks++) {
            uint32_t bh[4][2], bl[4][2];
            #pragma unroll
            for (int nt = 0; nt < 4; nt++) {
                ldsm_x2(bh[nt], bBaseHi + nt * 8 * (LDA * 2) + ks * 32);
                ldsm_x2(bl[nt], bBaseLo + nt * 8 * (LDA * 2) + ks * 32);
            }
            #pragma unroll
            for (int mt = 0; mt < 4; mt++) {
                uint32_t ah[4], al[4];
                ldsm_x4(ah, aBaseHi + mt * 16 * (LDA * 2) + ks * 32);
                ldsm_x4(al, aBaseLo + mt * 16 * (LDA * 2) + ks * 32);
                #pragma unroll
                for (int nt = 0; nt < 4; nt++) {
                    mma_bf16(acc[mt][nt], ah, bh[nt]);
                    mma_bf16(acc[mt][nt], ah, bl[nt]);
                    mma_bf16(acc[mt][nt], al, bh[nt]);
                }
            }
        }

        if (!doHead) {
            const int colOff = bt * 128;
            #pragma unroll
            for (int mt = 0; mt < 4; mt++) {
                #pragma unroll
                for (int nt = 0; nt < 4; nt++) {
                    int lc = wn + nt * 8 + (lane & 3) * 2;
                    int r0 = rowBase + wm + mt * 16 + (lane >> 2);
                    float b0 = bs[colOff + lc], b1 = bs[colOff + lc + 1];
                    int c = colOff + lc;
                    #pragma unroll
                    for (int half = 0; half < 2; half++) {
                        int r = r0 + half * 8;
                        if (r < NN) {
                            float vx = fmaxf(acc[mt][nt][half * 2 + 0] + b0, 0.f);
                            float vy = fmaxf(acc[mt][nt][half * 2 + 1] + b1, 0.f);
                            if (outMode == 0) {
                                float2 v; v.x = vx; v.y = vy;
                                *reinterpret_cast<float2*>(out + (size_t)r * outCols + c) = v;
                            } else {
                                __nv_bfloat162 h2 = __floats2bfloat162_rn(vx, vy);
                                float2 hf = __bfloat1622float2(h2);
                                __nv_bfloat162 l2 = __floats2bfloat162_rn(vx - hf.x, vy - hf.y);
                                oHi[r * 64 + (c >> 1)] = reinterpret_cast<uint32_t&>(h2);
                                oLo[r * 64 + (c >> 1)] = reinterpret_cast<uint32_t&>(l2);
                            }
                        }
                    }
                }
            }
        } else {
            // all warps must finish reading this bt's B tile before overwriting with h
            __syncthreads();
            const int hHi = bt ? (B_HI + 34816) : B_HI;
            const int hLo = bt ? (B_LO + 34816) : B_LO;
            const int colOff = bt * 128;
            #pragma unroll
            for (int mt = 0; mt < 4; mt++) {
                #pragma unroll
                for (int nt = 0; nt < 4; nt++) {
                    int lc = wn + nt * 8 + (lane & 3) * 2;
                    int lr = wm + mt * 16 + (lane >> 2);
                    float b0 = bs[colOff + lc], b1 = bs[colOff + lc + 1];
                    #pragma unroll
                    for (int half = 0; half < 2; half++) {
                        float vx = fmaxf(acc[mt][nt][half * 2 + 0] + b0, 0.f);
                        float vy = fmaxf(acc[mt][nt][half * 2 + 1] + b1, 0.f);
                        __nv_bfloat162 h2 = __floats2bfloat162_rn(vx, vy);
                        float2 hf = __bfloat1622float2(h2);
                        __nv_bfloat162 l2 = __floats2bfloat162_rn(vx - hf.x, vy - hf.y);
                        int r = lr + half * 8;
                        *reinterpret_cast<uint32_t*>(smem + hHi + r * (LDA * 2) + lc * 2) =
                            reinterpret_cast<uint32_t&>(h2);
                        *reinterpret_cast<uint32_t*>(smem + hLo + r * (LDA * 2) + lc * 2) =
                            reinterpret_cast<uint32_t&>(l2);
                    }
                }
            }
        }
    }

    if (doHead) {
        __syncthreads();   // all h tiles written
        const int slab = wid * 16;
        float acc2[2][4];
        #pragma unroll
        for (int nt = 0; nt < 2; nt++)
            #pragma unroll
            for (int j = 0; j < 4; j++) acc2[nt][j] = 0.f;

        const uint32_t aRowOff = (slab + (lane & 15)) * (LDA * 2) + (lane >> 4) * 16;
        const uint32_t bRowOff = (lane & 7) * 528 + ((lane >> 3) & 1) * 16;
        #pragma unroll
        for (int ks = 0; ks < 16; ks++) {
            const int half = ks >> 3, kl = ks & 7;
            uint32_t ah[4], al[4];
            ldsm_x4(ah, sb + (half ? B_HI + 34816 : B_HI) + aRowOff + kl * 32);
            ldsm_x4(al, sb + (half ? B_LO + 34816 : B_LO) + aRowOff + kl * 32);
            #pragma unroll
            for (int nt = 0; nt < 2; nt++) {
                uint32_t bh[2], bl[2];
                ldsm_x2(bh, sb + WM2_HI + bRowOff + nt * 8 * 528 + ks * 32);
                ldsm_x2(bl, sb + WM2_LO + bRowOff + nt * 8 * 528 + ks * 32);
                mma_bf16(acc2[nt], ah, bh);
                mma_bf16(acc2[nt], ah, bl);
                mma_bf16(acc2[nt], al, bh);
            }
        }
        #pragma unroll
        for (int nt = 0; nt < 2; nt++) {
            int c = nt * 8 + (lane & 3) * 2;
            if (c < 10) {
                float ba = bm2[c], bb = bm2[c + 1];
                int r0 = rowBase + slab + (lane >> 2);
                if (r0 < NN) {
                    float2 v; v.x = acc2[nt][0] + ba; v.y = acc2[nt][1] + bb;
                    *reinterpret_cast<float2*>(logits + (size_t)r0 * 10 + c) = v;
                }
                int r1 = r0 + 8;
                if (r1 < NN) {
                    float2 v; v.x = acc2[nt][2] + ba; v.y = acc2[nt][3] + bb;
                    *reinterpret_cast<float2*>(logits + (size_t)r1 * 10 + c) = v;
                }
            }
        }
    }
}

// ===================== host =====================
extern "C" void kernel_launch(void* const* d_in, const int* in_sizes, int n_in,
                              void* d_out, int out_size) {
    const float* x   = (const float*)d_in[0];
    const int*   ei  = (const int*)d_in[1];
    const float* W0  = (const float*)d_in[2];
    const float* b0  = (const float*)d_in[3];
    const float* W1  = (const float*)d_in[4];
    const float* b1  = (const float*)d_in[5];
    const float* W2  = (const float*)d_in[6];
    const float* b2  = (const float*)d_in[7];
    const float* Wm1 = (const float*)d_in[8];
    const float* bm1 = (const float*)d_in[9];
    const float* Wm2 = (const float*)d_in[10];
    const float* bm2 = (const float*)d_in[11];
    const int* src = ei;
    const int* dst = ei + NE;

    int *deg, *off, *cur, *srcs;
    unsigned long long* descs;
    float *bufF;
    __nv_bfloat16 *bufHi, *bufLo, *bufHi2, *bufLo2, *bhi, *blo;
    cudaGetSymbolAddress((void**)&deg,    g_deg);
    cudaGetSymbolAddress((void**)&off,    g_off);
    cudaGetSymbolAddress((void**)&cur,    g_cur);
    cudaGetSymbolAddress((void**)&srcs,   g_srcs);
    cudaGetSymbolAddress((void**)&descs,  g_descs);
    cudaGetSymbolAddress((void**)&bufF,   g_bufF);
    cudaGetSymbolAddress((void**)&bufHi,  g_bufHi);
    cudaGetSymbolAddress((void**)&bufLo,  g_bufLo);
    cudaGetSymbolAddress((void**)&bufHi2, g_bufHi2);
    cudaGetSymbolAddress((void**)&bufLo2, g_bufLo2);
    cudaGetSymbolAddress((void**)&bhi,    g_Bhi);
    cudaGetSymbolAddress((void**)&blo,    g_Blo);

    cudaFuncSetAttribute(gemm_tc_kernel,
                         cudaFuncAttributeMaxDynamicSharedMemorySize, SM_BYTES);

    // weight prep (+deg/descs zero) + CSR build
    prep_w_kernel<<<(PREP_TOTAL + 255) / 256, 256>>>(W0, W1, W2, Wm1, Wm2, bhi, blo,
                                                     deg, descs);
    hist_kernel<<<(NE + 255) / 256, 256>>>(dst, deg);
    scanfused_kernel<<<SCAN_BLOCKS, 1024>>>(deg, off, cur, descs);
    scatter_kernel<<<(NE + 255) / 256, 256>>>(src, dst, cur, srcs);

    const int warpBlocks = (NN * 32 + 255) / 256;
    const int gemmBlocks = (NN + 127) / 128;   // 391

    // layer 0
    agg_kernel<<<warpBlocks, 256>>>((const float4*)x, off, srcs,
                                    (uint2*)bufHi, (uint2*)bufLo);
    gemm_tc_kernel<<<gemmBlocks, 256, SM_BYTES>>>((const uint2*)bufHi, (const uint2*)bufLo,
                                                  bhi, blo, b0, bufF, nullptr, nullptr,
                                                  0, 128, 1, 0, 0, nullptr, nullptr);
    // layer 1
    agg_kernel<<<warpBlocks, 256>>>((const float4*)bufF, off, srcs,
                                    (uint2*)bufHi, (uint2*)bufLo);
    gemm_tc_kernel<<<gemmBlocks, 256, SM_BYTES>>>((const uint2*)bufHi, (const uint2*)bufLo,
                                                  bhi, blo, b1, bufF, nullptr, nullptr,
                                                  1, 128, 1, 0, 0, nullptr, nullptr);
    // layer 2
    agg_kernel<<<warpBlocks, 256>>>((const float4*)bufF, off, srcs,
                                    (uint2*)bufHi, (uint2*)bufLo);
    gemm_tc_kernel<<<gemmBlocks, 256, SM_BYTES>>>((const uint2*)bufHi, (const uint2*)bufLo,
                                                  bhi, blo, b2, nullptr,
                                                  (uint32_t*)bufHi2, (uint32_t*)bufLo2,
                                                  2, 128, 1, 1, 0, nullptr, nullptr);
    // MLP hidden (both column tiles) + head, fully fused; logits straight to d_out
    gemm_tc_kernel<<<gemmBlocks, 256, SM_BYTES>>>((const uint2*)bufHi2, (const uint2*)bufLo2,
                                                  bhi, blo, bm1, nullptr, nullptr, nullptr,
                                                  3, 256, 2, 0, 1, (float*)d_out, bm2);
}